// round 4
// baseline (speedup 1.0000x reference)
#include <cuda_runtime.h>
#include <math.h>

// OmegaRule: B=8, L=8192, D=256, W=64 -> NW=128 windows, T=B*W=512 rows/window.
#define BB 8
#define LL 8192
#define DD 256
#define WW 64
#define NW 128
#define TT 512
#define CH 8     // chunks
#define CS 16    // windows per chunk (CH*CS == NW)
#define MATSZ (DD * DD)
#define RA 8     // rows (of M and of P) per CTA in scan kernels

// Scratch (device globals; no allocation allowed).
__device__ float g_Skk[NW * MATSZ];
__device__ float g_Svk[NW * MATSZ];
__device__ float g_Ms [NW * MATSZ];   // phase A: local scans; phase C: fixed in place
__device__ float g_P  [NW * MATSZ];   // within-chunk prefix products of A = aI - Skk
__device__ float g_E  [CH * MATSZ];   // chunk-end global states

// ---- packed fp32x2 helpers (Blackwell FFMA2 — PTX-only path) --------------
typedef unsigned long long u64;
__device__ __forceinline__ void ffma2(u64& acc, u64 a, u64 b) {
    asm("fma.rn.f32x2 %0, %1, %2, %0;" : "+l"(acc) : "l"(a), "l"(b));
}
__device__ __forceinline__ u64 pack2f(float x, float y) {
    u64 r; asm("mov.b64 %0, {%1, %2};" : "=l"(r) : "f"(x), "f"(y)); return r;
}
__device__ __forceinline__ void unpack2f(u64 v, float& x, float& y) {
    asm("mov.b64 {%0, %1}, %2;" : "=f"(x), "=f"(y) : "l"(v));
}

// ---------------------------------------------------------------------------
// K1: per-window moment matrices.
//   Skk[n] = sum_t g_t k_t k_t^T  (symmetric: computed only for ib<=jb, mirrored)
//   Svk[n] = sum_t g_t v_t k_t^T  (all 16 tiles)
// grid = (16 tiles, NW), block = 256; 4x4 micro with row-paired FFMA2.
// ---------------------------------------------------------------------------
__global__ __launch_bounds__(256) void k1_moments(
    const float* __restrict__ keys,
    const float* __restrict__ values,
    const float* __restrict__ gammas)
{
    __shared__ float4 sGK[16][16];
    __shared__ float4 sGV[16][16];
    __shared__ float4 sK [16][16];

    const int n   = blockIdx.y;
    const int ib  = blockIdx.x >> 2;
    const int jb  = blockIdx.x & 3;
    const bool doSkk = (ib <= jb);
    const int tid = threadIdx.x;
    const int tr  = tid >> 4;
    const int tc  = tid & 15;
    const int tx  = tid & 15;
    const int ty  = tid >> 4;

    u64 aV0[4] = {0,0,0,0}, aV1[4] = {0,0,0,0};   // Svk rows (0,1) and (2,3)
    u64 aS0[4] = {0,0,0,0}, aS1[4] = {0,0,0,0};   // Skk rows (0,1) and (2,3)

    for (int ch = 0; ch < TT / 16; ++ch) {
        const int t = ch * 16 + tr;
        const int b = t >> 6;
        const int w = t & 63;
        const long row = ((long)b * LL + (long)n * WW + w) * DD;
        const float g = __ldg(&gammas[(long)b * LL + (long)n * WW + w]);
        float4 vx = *(const float4*)(values + row + ib * 64 + tc * 4);
        float4 ky = *(const float4*)(keys   + row + jb * 64 + tc * 4);
        sGV[tr][tc] = make_float4(g * vx.x, g * vx.y, g * vx.z, g * vx.w);
        sK [tr][tc] = ky;
        if (doSkk) {
            float4 kx = *(const float4*)(keys + row + ib * 64 + tc * 4);
            sGK[tr][tc] = make_float4(g * kx.x, g * kx.y, g * kx.z, g * kx.w);
        }
        __syncthreads();

        if (doSkk) {
            #pragma unroll
            for (int tk = 0; tk < 16; ++tk) {
                float4 a1 = sGK[tk][ty];
                float4 a2 = sGV[tk][ty];
                float4 bb = sK [tk][tx];
                u64 a1p0 = pack2f(a1.x, a1.y), a1p1 = pack2f(a1.z, a1.w);
                u64 a2p0 = pack2f(a2.x, a2.y), a2p1 = pack2f(a2.z, a2.w);
                float bv[4] = {bb.x, bb.y, bb.z, bb.w};
                #pragma unroll
                for (int c = 0; c < 4; ++c) {
                    u64 bp = pack2f(bv[c], bv[c]);
                    ffma2(aV0[c], a2p0, bp); ffma2(aV1[c], a2p1, bp);
                    ffma2(aS0[c], a1p0, bp); ffma2(aS1[c], a1p1, bp);
                }
            }
        } else {
            #pragma unroll
            for (int tk = 0; tk < 16; ++tk) {
                float4 a2 = sGV[tk][ty];
                float4 bb = sK [tk][tx];
                u64 a2p0 = pack2f(a2.x, a2.y), a2p1 = pack2f(a2.z, a2.w);
                float bv[4] = {bb.x, bb.y, bb.z, bb.w};
                #pragma unroll
                for (int c = 0; c < 4; ++c) {
                    u64 bp = pack2f(bv[c], bv[c]);
                    ffma2(aV0[c], a2p0, bp); ffma2(aV1[c], a2p1, bp);
                }
            }
        }
        __syncthreads();
    }

    float V[4][4];
    #pragma unroll
    for (int c = 0; c < 4; ++c) {
        unpack2f(aV0[c], V[0][c], V[1][c]);
        unpack2f(aV1[c], V[2][c], V[3][c]);
    }
    float* svk = g_Svk + (long)n * MATSZ;
    #pragma unroll
    for (int r = 0; r < 4; ++r) {
        const int x  = ib * 64 + ty * 4 + r;
        const int y0 = jb * 64 + tx * 4;
        *(float4*)(svk + (long)x * DD + y0) =
            make_float4(V[r][0], V[r][1], V[r][2], V[r][3]);
    }

    if (doSkk) {
        float S[4][4];
        #pragma unroll
        for (int c = 0; c < 4; ++c) {
            unpack2f(aS0[c], S[0][c], S[1][c]);
            unpack2f(aS1[c], S[2][c], S[3][c]);
        }
        float* skk = g_Skk + (long)n * MATSZ;
        #pragma unroll
        for (int r = 0; r < 4; ++r) {
            const int x  = ib * 64 + ty * 4 + r;
            const int y0 = jb * 64 + tx * 4;
            *(float4*)(skk + (long)x * DD + y0) =
                make_float4(S[r][0], S[r][1], S[r][2], S[r][3]);
        }
        if (ib < jb) {   // mirror into the transposed tile
            #pragma unroll
            for (int r = 0; r < 4; ++r)
                #pragma unroll
                for (int c = 0; c < 4; ++c) {
                    const int x = ib * 64 + ty * 4 + r;
                    const int y = jb * 64 + tx * 4 + c;
                    skk[(long)y * DD + x] = S[r][c];
                }
        }
    }
}

// ---------------------------------------------------------------------------
// Phase A: per-chunk local scan + prefix products, LSU-lean layout.
// CTA: 256 thr; thread (q = tid&31 -> cols 8q..8q+7, g = tid>>5 -> row o0+g).
// CTA owns RA=8 M-rows and 8 P-rows. Skk staged to smem double-buffered.
//   m <- a*m - m@Skk + svk_row   (zero init)
//   p <- a*p - p@Skk             (identity init; only when DOP)
// grid = (DD/RA, #chunks), block = 256.
// ---------------------------------------------------------------------------
template<bool DOP>
__global__ __launch_bounds__(256) void kA_local(const float* __restrict__ alpha_p,
                                                int chunk0)
{
    __shared__ float sS[2][16 * 256];   // 32 KB double-buffered Skk block
    __shared__ float sM[RA * 256];
    __shared__ float sP[RA * 256];

    const int tid = threadIdx.x;
    const int q = tid & 31;
    const int g = tid >> 5;
    const int c = chunk0 + blockIdx.y;
    const int o0 = blockIdx.x * RA;
    const float a = 1.f / (1.f + expf(-alpha_p[0]));

    #pragma unroll
    for (int i = 0; i < 8; ++i) {
        const int col = q * 8 + i;
        sM[g * 256 + col] = 0.f;
        sP[g * 256 + col] = (col == o0 + g) ? 1.f : 0.f;
    }
    __syncthreads();

    for (int s = 0; s < CS; ++s) {
        const int n = c * CS + s;
        const float* skk = g_Skk + (long)n * MATSZ;
        const float* svk = g_Svk + (long)n * MATSZ;

        float4 stg[4];
        #pragma unroll
        for (int i = 0; i < 4; ++i)
            stg[i] = *(const float4*)(skk + 4 * (tid + i * 256));

        u64 accM[4] = {0,0,0,0};
        u64 accP[4] = {0,0,0,0};

        for (int bi = 0; bi < 16; ++bi) {
            float* buf = sS[bi & 1];
            #pragma unroll
            for (int i = 0; i < 4; ++i)
                *(float4*)(buf + 4 * (tid + i * 256)) = stg[i];
            __syncthreads();
            if (bi < 15) {
                const float* src = skk + (long)(bi + 1) * 4096;
                #pragma unroll
                for (int i = 0; i < 4; ++i)
                    stg[i] = *(const float4*)(src + 4 * (tid + i * 256));
            }

            float mv[16], pv[16];
            const float* mrow = &sM[g * 256 + bi * 16];
            #pragma unroll
            for (int d = 0; d < 16; ++d) mv[d] = mrow[d];
            if (DOP) {
                const float* prow = &sP[g * 256 + bi * 16];
                #pragma unroll
                for (int d = 0; d < 16; ++d) pv[d] = prow[d];
            }

            #pragma unroll
            for (int d = 0; d < 16; ++d) {
                const float4 s0 = *(const float4*)(buf + d * 256 + q * 8);
                const float4 s1 = *(const float4*)(buf + d * 256 + q * 8 + 4);
                u64 sp0 = pack2f(s0.x, s0.y), sp1 = pack2f(s0.z, s0.w);
                u64 sp2 = pack2f(s1.x, s1.y), sp3 = pack2f(s1.z, s1.w);
                u64 mm = pack2f(mv[d], mv[d]);
                ffma2(accM[0], mm, sp0); ffma2(accM[1], mm, sp1);
                ffma2(accM[2], mm, sp2); ffma2(accM[3], mm, sp3);
                if (DOP) {
                    u64 pp = pack2f(pv[d], pv[d]);
                    ffma2(accP[0], pp, sp0); ffma2(accP[1], pp, sp1);
                    ffma2(accP[2], pp, sp2); ffma2(accP[3], pp, sp3);
                }
            }
        }

        // epilogue
        float dotM[8], dotP[8];
        #pragma unroll
        for (int i = 0; i < 4; ++i) unpack2f(accM[i], dotM[2*i], dotM[2*i+1]);
        if (DOP) {
            #pragma unroll
            for (int i = 0; i < 4; ++i) unpack2f(accP[i], dotP[2*i], dotP[2*i+1]);
        }

        float4 mo0 = *(const float4*)&sM[g * 256 + q * 8];
        float4 mo1 = *(const float4*)&sM[g * 256 + q * 8 + 4];
        float mold[8] = {mo0.x, mo0.y, mo0.z, mo0.w, mo1.x, mo1.y, mo1.z, mo1.w};
        float4 sv0 = *(const float4*)(svk + (long)(o0 + g) * DD + q * 8);
        float4 sv1 = *(const float4*)(svk + (long)(o0 + g) * DD + q * 8 + 4);
        float svv[8] = {sv0.x, sv0.y, sv0.z, sv0.w, sv1.x, sv1.y, sv1.z, sv1.w};

        float nM[8], nP[8];
        #pragma unroll
        for (int i = 0; i < 8; ++i) nM[i] = a * mold[i] - dotM[i] + svv[i];
        if (DOP) {
            float4 po0 = *(const float4*)&sP[g * 256 + q * 8];
            float4 po1 = *(const float4*)&sP[g * 256 + q * 8 + 4];
            float pold[8] = {po0.x, po0.y, po0.z, po0.w, po1.x, po1.y, po1.z, po1.w};
            #pragma unroll
            for (int i = 0; i < 8; ++i) nP[i] = a * pold[i] - dotP[i];
        }
        __syncthreads();   // all reads of sM/sP done

        *(float4*)&sM[g * 256 + q * 8]     = make_float4(nM[0], nM[1], nM[2], nM[3]);
        *(float4*)&sM[g * 256 + q * 8 + 4] = make_float4(nM[4], nM[5], nM[6], nM[7]);
        float* ms = g_Ms + (long)n * MATSZ + (long)(o0 + g) * DD + q * 8;
        *(float4*)(ms)     = make_float4(nM[0], nM[1], nM[2], nM[3]);
        *(float4*)(ms + 4) = make_float4(nM[4], nM[5], nM[6], nM[7]);
        if (DOP) {
            *(float4*)&sP[g * 256 + q * 8]     = make_float4(nP[0], nP[1], nP[2], nP[3]);
            *(float4*)&sP[g * 256 + q * 8 + 4] = make_float4(nP[4], nP[5], nP[6], nP[7]);
            float* pp = g_P + (long)n * MATSZ + (long)(o0 + g) * DD + q * 8;
            *(float4*)(pp)     = make_float4(nP[0], nP[1], nP[2], nP[3]);
            *(float4*)(pp + 4) = make_float4(nP[4], nP[5], nP[6], nP[7]);
        }
        __syncthreads();   // writes visible before next window's scalar reads
    }
}

// ---------------------------------------------------------------------------
// Phase B: sequential combine over chunk ends.
//   E_0 = Mloc_end(chunk 0);  E_c = E_{c-1} @ P_end(c) + Mloc_end(c)
// Same LSU-lean layout; rows are independent so sE persists in smem.
// grid = DD/RA = 32, block = 256.
// ---------------------------------------------------------------------------
__global__ __launch_bounds__(256) void kB_combine()
{
    __shared__ float sS[2][16 * 256];
    __shared__ float sE[RA * 256];

    const int tid = threadIdx.x;
    const int q = tid & 31;
    const int g = tid >> 5;
    const int o0 = blockIdx.x * RA;

    {   // E_0 from chunk-0 end
        const float* m0 = g_Ms + (long)(CS - 1) * MATSZ + (long)(o0 + g) * DD + q * 8;
        float* e0 = g_E + (long)(o0 + g) * DD + q * 8;
        float4 v0 = *(const float4*)(m0);
        float4 v1 = *(const float4*)(m0 + 4);
        *(float4*)&sE[g * 256 + q * 8]     = v0;
        *(float4*)&sE[g * 256 + q * 8 + 4] = v1;
        *(float4*)(e0)     = v0;
        *(float4*)(e0 + 4) = v1;
    }
    __syncthreads();

    for (int cc = 1; cc < CH; ++cc) {
        const long base = (long)(cc * CS + CS - 1) * MATSZ;
        const float* pm = g_P  + base;
        const float* mm = g_Ms + base;

        float4 stg[4];
        #pragma unroll
        for (int i = 0; i < 4; ++i)
            stg[i] = *(const float4*)(pm + 4 * (tid + i * 256));

        u64 accE[4] = {0,0,0,0};

        for (int bi = 0; bi < 16; ++bi) {
            float* buf = sS[bi & 1];
            #pragma unroll
            for (int i = 0; i < 4; ++i)
                *(float4*)(buf + 4 * (tid + i * 256)) = stg[i];
            __syncthreads();
            if (bi < 15) {
                const float* src = pm + (long)(bi + 1) * 4096;
                #pragma unroll
                for (int i = 0; i < 4; ++i)
                    stg[i] = *(const float4*)(src + 4 * (tid + i * 256));
            }

            float ev[16];
            const float* erow = &sE[g * 256 + bi * 16];
            #pragma unroll
            for (int d = 0; d < 16; ++d) ev[d] = erow[d];

            #pragma unroll
            for (int d = 0; d < 16; ++d) {
                const float4 s0 = *(const float4*)(buf + d * 256 + q * 8);
                const float4 s1 = *(const float4*)(buf + d * 256 + q * 8 + 4);
                u64 sp0 = pack2f(s0.x, s0.y), sp1 = pack2f(s0.z, s0.w);
                u64 sp2 = pack2f(s1.x, s1.y), sp3 = pack2f(s1.z, s1.w);
                u64 ee = pack2f(ev[d], ev[d]);
                ffma2(accE[0], ee, sp0); ffma2(accE[1], ee, sp1);
                ffma2(accE[2], ee, sp2); ffma2(accE[3], ee, sp3);
            }
        }

        float dotE[8];
        #pragma unroll
        for (int i = 0; i < 4; ++i) unpack2f(accE[i], dotE[2*i], dotE[2*i+1]);
        const float* mrow = mm + (long)(o0 + g) * DD + q * 8;
        float4 me0 = *(const float4*)(mrow);
        float4 me1 = *(const float4*)(mrow + 4);
        float mev[8] = {me0.x, me0.y, me0.z, me0.w, me1.x, me1.y, me1.z, me1.w};
        float nE[8];
        #pragma unroll
        for (int i = 0; i < 8; ++i) nE[i] = dotE[i] + mev[i];
        __syncthreads();
        *(float4*)&sE[g * 256 + q * 8]     = make_float4(nE[0], nE[1], nE[2], nE[3]);
        *(float4*)&sE[g * 256 + q * 8 + 4] = make_float4(nE[4], nE[5], nE[6], nE[7]);
        float* e = g_E + (long)cc * MATSZ + (long)(o0 + g) * DD + q * 8;
        *(float4*)(e)     = make_float4(nE[0], nE[1], nE[2], nE[3]);
        *(float4*)(e + 4) = make_float4(nE[4], nE[5], nE[6], nE[7]);
        __syncthreads();
    }
}

// ---------------------------------------------------------------------------
// Phase C: fix-up GEMMs (parallel): Ms[n] += E_{c-1} @ P_n  for chunks 1..7.
// 64x64 tiles, 4x4 micro with row-paired FFMA2; padding 68 keeps LDS.128 aligned.
// ---------------------------------------------------------------------------
__global__ __launch_bounds__(256) void kC_fix()
{
    __shared__ float sE[16][68];
    __shared__ float sP[16][68];

    const int nw  = blockIdx.y + CS;
    const int c   = nw >> 4;
    const int ib  = blockIdx.x >> 2;
    const int jb  = blockIdx.x & 3;
    const int tid = threadIdx.x;
    const int lr  = tid >> 2;
    const int lc  = tid & 3;
    const int pr  = tid >> 4;
    const int pc  = tid & 15;
    const int tx  = tid & 15;
    const int ty  = tid >> 4;

    const float* E = g_E + (long)(c - 1) * MATSZ;
    const float* P = g_P + (long)nw * MATSZ;
    float*      Ms = g_Ms + (long)nw * MATSZ;

    u64 acc0[4] = {0,0,0,0}, acc1[4] = {0,0,0,0};

    const long erow = (long)(ib * 64 + lr) * DD;

    for (int ch = 0; ch < 16; ++ch) {
        float4 ev = *(const float4*)(E + erow + ch * 16 + lc * 4);
        float4 pv = *(const float4*)(P + (long)(ch * 16 + pr) * DD + jb * 64 + pc * 4);
        sE[lc * 4 + 0][lr] = ev.x; sE[lc * 4 + 1][lr] = ev.y;
        sE[lc * 4 + 2][lr] = ev.z; sE[lc * 4 + 3][lr] = ev.w;
        sP[pr][pc * 4 + 0] = pv.x; sP[pr][pc * 4 + 1] = pv.y;
        sP[pr][pc * 4 + 2] = pv.z; sP[pr][pc * 4 + 3] = pv.w;
        __syncthreads();

        #pragma unroll
        for (int dk = 0; dk < 16; ++dk) {
            float4 av = *(const float4*)&sE[dk][ty * 4];
            float4 bv = *(const float4*)&sP[dk][tx * 4];
            u64 a01 = pack2f(av.x, av.y), a23 = pack2f(av.z, av.w);
            float bb[4] = {bv.x, bv.y, bv.z, bv.w};
            #pragma unroll
            for (int q = 0; q < 4; ++q) {
                u64 bp = pack2f(bb[q], bb[q]);
                ffma2(acc0[q], a01, bp);
                ffma2(acc1[q], a23, bp);
            }
        }
        __syncthreads();
    }

    float A[4][4];
    #pragma unroll
    for (int q = 0; q < 4; ++q) {
        unpack2f(acc0[q], A[0][q], A[1][q]);
        unpack2f(acc1[q], A[2][q], A[3][q]);
    }
    #pragma unroll
    for (int r = 0; r < 4; ++r) {
        float* dst = Ms + (long)(ib * 64 + ty * 4 + r) * DD + jb * 64 + tx * 4;
        float4 old = *(const float4*)dst;
        *(float4*)dst = make_float4(old.x + A[r][0], old.y + A[r][1],
                                    old.z + A[r][2], old.w + A[r][3]);
    }
}

// ---------------------------------------------------------------------------
// K3: retrieval. out[t][o] = sum_d q[t][d] * Ms[n][o][d]
// Row-paired FFMA2 micro; padding 68 for aligned LDS.128.
// ---------------------------------------------------------------------------
__global__ __launch_bounds__(256) void k3_out(
    const float* __restrict__ queries, float* __restrict__ out)
{
    __shared__ float sQ[16][68];
    __shared__ float sM[16][68];

    const int n   = blockIdx.y;
    const int tb  = blockIdx.x >> 2;
    const int ob  = blockIdx.x & 3;
    const int tid = threadIdx.x;
    const int lr  = tid >> 2;
    const int lc  = tid & 3;
    const int tx  = tid & 15;
    const int ty  = tid >> 4;

    const float* Ms = g_Ms + (long)n * MATSZ;

    u64 acc0[4] = {0,0,0,0}, acc1[4] = {0,0,0,0};

    const int t_ld = tb * 64 + lr;
    const int b_ld = t_ld >> 6;
    const int w_ld = t_ld & 63;
    const long qrow = ((long)b_ld * LL + (long)n * WW + w_ld) * DD;
    const long mrow = (long)(ob * 64 + lr) * DD;

    for (int ch = 0; ch < 16; ++ch) {
        float4 qv = *(const float4*)(queries + qrow + ch * 16 + lc * 4);
        float4 mv = *(const float4*)(Ms + mrow + ch * 16 + lc * 4);
        sQ[lc * 4 + 0][lr] = qv.x; sQ[lc * 4 + 1][lr] = qv.y;
        sQ[lc * 4 + 2][lr] = qv.z; sQ[lc * 4 + 3][lr] = qv.w;
        sM[lc * 4 + 0][lr] = mv.x; sM[lc * 4 + 1][lr] = mv.y;
        sM[lc * 4 + 2][lr] = mv.z; sM[lc * 4 + 3][lr] = mv.w;
        __syncthreads();

        #pragma unroll
        for (int dk = 0; dk < 16; ++dk) {
            float4 av = *(const float4*)&sQ[dk][ty * 4];
            float4 bv = *(const float4*)&sM[dk][tx * 4];
            u64 a01 = pack2f(av.x, av.y), a23 = pack2f(av.z, av.w);
            float bb[4] = {bv.x, bv.y, bv.z, bv.w};
            #pragma unroll
            for (int q = 0; q < 4; ++q) {
                u64 bp = pack2f(bb[q], bb[q]);
                ffma2(acc0[q], a01, bp);
                ffma2(acc1[q], a23, bp);
            }
        }
        __syncthreads();
    }

    float A[4][4];
    #pragma unroll
    for (int q = 0; q < 4; ++q) {
        unpack2f(acc0[q], A[0][q], A[1][q]);
        unpack2f(acc1[q], A[2][q], A[3][q]);
    }
    #pragma unroll
    for (int r = 0; r < 4; ++r) {
        const int t = tb * 64 + ty * 4 + r;
        const int b = t >> 6;
        const int w = t & 63;
        const long addr = ((long)b * LL + (long)n * WW + w) * DD + ob * 64 + tx * 4;
        *(float4*)(out + addr) = make_float4(A[r][0], A[r][1], A[r][2], A[r][3]);
    }
}

// ---------------------------------------------------------------------------
extern "C" void kernel_launch(void* const* d_in, const int* in_sizes, int n_in,
                              void* d_out, int out_size)
{
    const float* keys    = (const float*)d_in[0];
    const float* values  = (const float*)d_in[1];
    const float* queries = (const float*)d_in[2];
    const float* gammas  = (const float*)d_in[3];
    const float* alpha   = (const float*)d_in[4];
    float* out = (float*)d_out;

    k1_moments<<<dim3(16, NW), 256>>>(keys, values, gammas);
    kA_local<false><<<dim3(DD / RA, 1), 256>>>(alpha, 0);       // chunk 0 (no P)
    kA_local<true ><<<dim3(DD / RA, CH - 1), 256>>>(alpha, 1);  // chunks 1..7
    kB_combine<<<DD / RA, 256>>>();
    kC_fix<<<dim3(16, NW - CS), 256>>>();
    k3_out<<<dim3(32, NW), 256>>>(queries, out);
}

// round 5
// speedup vs baseline: 1.5058x; 1.5058x over previous
#include <cuda_runtime.h>
#include <math.h>

// OmegaRule: B=8, L=8192, D=256, W=64 -> NW=128 windows, T=B*W=512 rows/window.
#define BB 8
#define LL 8192
#define DD 256
#define WW 64
#define NW 128
#define TT 512
#define CH 16    // chunks
#define CS 8     // windows per chunk (CH*CS == NW)
#define MATSZ (DD * DD)

// Scratch (device globals; no allocation allowed).
__device__ float g_Skk[NW * MATSZ];
__device__ float g_Svk[NW * MATSZ];
__device__ float g_Ms [NW * MATSZ];   // phase A: local scans; fix-up adds in place
__device__ float g_P  [NW * MATSZ];   // within-chunk prefix products of A = aI - Skk
// tree-combine ping-pong buffers over CH chunk summaries
__device__ float g_TP0[CH * MATSZ];
__device__ float g_TP1[CH * MATSZ];
__device__ float g_TS0[CH * MATSZ];
__device__ float g_TS1[CH * MATSZ];

typedef unsigned long long u64;
__device__ __forceinline__ void ffma2(u64& acc, u64 a, u64 b) {
    asm("fma.rn.f32x2 %0, %1, %2, %0;" : "+l"(acc) : "l"(a), "l"(b));
}
__device__ __forceinline__ u64 pack2f(float x, float y) {
    u64 r; asm("mov.b64 %0, {%1, %2};" : "=l"(r) : "f"(x), "f"(y)); return r;
}
__device__ __forceinline__ void unpack2f(u64 v, float& x, float& y) {
    asm("mov.b64 {%0, %1}, %2;" : "=f"(x), "=f"(y) : "l"(v));
}
__device__ __forceinline__ float hsum2(u64 v) {
    float x, y; unpack2f(v, x, y); return x + y;
}

// ---------------------------------------------------------------------------
// K1: per-window moment matrices.
//   Skk[n] = sum_t g_t k_t k_t^T   (symmetric: computed for ib<=jb, mirrored)
//   Svk[n] = sum_t g_t v_t k_t^T   (all 16 tiles)
// grid = (16 tiles, NW), block = 256; register prefetch double-buffer-lite.
// ---------------------------------------------------------------------------
__global__ __launch_bounds__(256) void k1_moments(
    const float* __restrict__ keys,
    const float* __restrict__ values,
    const float* __restrict__ gammas)
{
    __shared__ float4 sGK[16][16];
    __shared__ float4 sGV[16][16];
    __shared__ float4 sK [16][16];

    const int n   = blockIdx.y;
    const int ib  = blockIdx.x >> 2;
    const int jb  = blockIdx.x & 3;
    const bool doSkk = (ib <= jb);
    const int tid = threadIdx.x;
    const int tr  = tid >> 4;
    const int tc  = tid & 15;
    const int tx  = tid & 15;
    const int ty  = tid >> 4;

    float acc1[4][4], acc2[4][4];
    #pragma unroll
    for (int r = 0; r < 4; ++r)
        #pragma unroll
        for (int c = 0; c < 4; ++c) { acc1[r][c] = 0.f; acc2[r][c] = 0.f; }

    // prefetch chunk 0
    float g; float4 kx, vx, ky;
    {
        const int t = tr;
        const int b = t >> 6;
        const int w = t & 63;
        const long row = ((long)b * LL + (long)n * WW + w) * DD;
        g  = __ldg(&gammas[(long)b * LL + (long)n * WW + w]);
        vx = *(const float4*)(values + row + ib * 64 + tc * 4);
        ky = *(const float4*)(keys   + row + jb * 64 + tc * 4);
        kx = *(const float4*)(keys   + row + ib * 64 + tc * 4);
    }

    for (int ch = 0; ch < TT / 16; ++ch) {
        sGV[tr][tc] = make_float4(g * vx.x, g * vx.y, g * vx.z, g * vx.w);
        sK [tr][tc] = ky;
        if (doSkk)
            sGK[tr][tc] = make_float4(g * kx.x, g * kx.y, g * kx.z, g * kx.w);
        __syncthreads();

        if (ch < TT / 16 - 1) {
            const int t = (ch + 1) * 16 + tr;
            const int b = t >> 6;
            const int w = t & 63;
            const long row = ((long)b * LL + (long)n * WW + w) * DD;
            g  = __ldg(&gammas[(long)b * LL + (long)n * WW + w]);
            vx = *(const float4*)(values + row + ib * 64 + tc * 4);
            ky = *(const float4*)(keys   + row + jb * 64 + tc * 4);
            if (doSkk) kx = *(const float4*)(keys + row + ib * 64 + tc * 4);
        }

        if (doSkk) {
            #pragma unroll
            for (int tk = 0; tk < 16; ++tk) {
                float4 a1 = sGK[tk][ty];
                float4 a2 = sGV[tk][ty];
                float4 bb = sK [tk][tx];
                float av1[4] = {a1.x, a1.y, a1.z, a1.w};
                float av2[4] = {a2.x, a2.y, a2.z, a2.w};
                float bv [4] = {bb.x, bb.y, bb.z, bb.w};
                #pragma unroll
                for (int r = 0; r < 4; ++r)
                    #pragma unroll
                    for (int c = 0; c < 4; ++c) {
                        acc1[r][c] += av1[r] * bv[c];
                        acc2[r][c] += av2[r] * bv[c];
                    }
            }
        } else {
            #pragma unroll
            for (int tk = 0; tk < 16; ++tk) {
                float4 a2 = sGV[tk][ty];
                float4 bb = sK [tk][tx];
                float av2[4] = {a2.x, a2.y, a2.z, a2.w};
                float bv [4] = {bb.x, bb.y, bb.z, bb.w};
                #pragma unroll
                for (int r = 0; r < 4; ++r)
                    #pragma unroll
                    for (int c = 0; c < 4; ++c)
                        acc2[r][c] += av2[r] * bv[c];
            }
        }
        __syncthreads();
    }

    float* svk = g_Svk + (long)n * MATSZ;
    #pragma unroll
    for (int r = 0; r < 4; ++r) {
        const int x  = ib * 64 + ty * 4 + r;
        const int y0 = jb * 64 + tx * 4;
        *(float4*)(svk + (long)x * DD + y0) =
            make_float4(acc2[r][0], acc2[r][1], acc2[r][2], acc2[r][3]);
    }
    if (doSkk) {
        float* skk = g_Skk + (long)n * MATSZ;
        #pragma unroll
        for (int r = 0; r < 4; ++r) {
            const int x  = ib * 64 + ty * 4 + r;
            const int y0 = jb * 64 + tx * 4;
            *(float4*)(skk + (long)x * DD + y0) =
                make_float4(acc1[r][0], acc1[r][1], acc1[r][2], acc1[r][3]);
        }
        if (ib < jb) {
            #pragma unroll
            for (int r = 0; r < 4; ++r)
                #pragma unroll
                for (int c = 0; c < 4; ++c) {
                    const int x = ib * 64 + ty * 4 + r;
                    const int y = jb * 64 + tx * 4 + c;
                    skk[(long)y * DD + x] = acc1[r][c];
                }
        }
    }
}

// ---------------------------------------------------------------------------
// Phase A: per-chunk local scan + prefix products (R3 conflict-free layout).
//   M rows:  m <- a*m - m@Skk + svk_row   (zero init)
//   P rows:  p <- a*p - p@Skk             (identity init)
// grid = (64 row-groups, CH chunks), block = 256. Thread j owns column j.
// ---------------------------------------------------------------------------
__global__ __launch_bounds__(256) void kA_local(const float* __restrict__ alpha_p)
{
    __shared__ float srow[8][DD];   // rows 0-3: M, rows 4-7: P
    const int j  = threadIdx.x;
    const int c  = blockIdx.y;
    const int o0 = blockIdx.x * 4;
    const float a = 1.f / (1.f + expf(-alpha_p[0]));

    #pragma unroll
    for (int r = 0; r < 4; ++r) {
        srow[r][j] = 0.f;
        srow[4 + r][j] = (j == o0 + r) ? 1.f : 0.f;
    }
    __syncthreads();

    for (int s = 0; s < CS; ++s) {
        const int n = c * CS + s;
        const float* skk = g_Skk + (long)n * MATSZ;
        const float* svk = g_Svk + (long)n * MATSZ;

        const float sv0 = svk[(long)(o0 + 0) * DD + j];
        const float sv1 = svk[(long)(o0 + 1) * DD + j];
        const float sv2 = svk[(long)(o0 + 2) * DD + j];
        const float sv3 = svk[(long)(o0 + 3) * DD + j];

        u64 accM[4] = {0, 0, 0, 0};
        u64 accP[4] = {0, 0, 0, 0};

        float sb[16];
        #pragma unroll
        for (int u = 0; u < 16; ++u) sb[u] = skk[(long)u * DD + j];

        #pragma unroll
        for (int blk = 0; blk < 16; ++blk) {
            float sn[16];
            if (blk < 15) {
                const float* p = skk + (long)(blk + 1) * 16 * DD + j;
                #pragma unroll
                for (int u = 0; u < 16; ++u) sn[u] = p[(long)u * DD];
            } else {
                #pragma unroll
                for (int u = 0; u < 16; ++u) sn[u] = 0.f;
            }
            u64 sp[8];
            #pragma unroll
            for (int p = 0; p < 8; ++p) sp[p] = pack2f(sb[2 * p], sb[2 * p + 1]);

            const int db = blk * 16;
            #pragma unroll
            for (int r = 0; r < 4; ++r) {
                const u64* mrow = (const u64*)&srow[r][db];
                #pragma unroll
                for (int p = 0; p < 8; ++p) ffma2(accM[r], mrow[p], sp[p]);
            }
            #pragma unroll
            for (int r = 0; r < 4; ++r) {
                const u64* prow = (const u64*)&srow[4 + r][db];
                #pragma unroll
                for (int p = 0; p < 8; ++p) ffma2(accP[r], prow[p], sp[p]);
            }
            #pragma unroll
            for (int u = 0; u < 16; ++u) sb[u] = sn[u];
        }

        float nM[4], nP[4];
        const float svv[4] = {sv0, sv1, sv2, sv3};
        #pragma unroll
        for (int r = 0; r < 4; ++r) {
            nM[r] = a * srow[r][j] - hsum2(accM[r]) + svv[r];
            nP[r] = a * srow[4 + r][j] - hsum2(accP[r]);
        }
        __syncthreads();
        float* ms = g_Ms + (long)n * MATSZ;
        float* pp = g_P  + (long)n * MATSZ;
        #pragma unroll
        for (int r = 0; r < 4; ++r) {
            srow[r][j] = nM[r];
            srow[4 + r][j] = nP[r];
            ms[(long)(o0 + r) * DD + j] = nM[r];
            pp[(long)(o0 + r) * DD + j] = nP[r];
        }
        __syncthreads();
    }
}

// ---------------------------------------------------------------------------
// Tree init: gather chunk-end summaries into ping-pong buffer 0.
//   TP0[c] = P[c*CS + CS-1],  TS0[c] = Ms[c*CS + CS-1]
// grid = (64, CH), block = 256.
// ---------------------------------------------------------------------------
__global__ __launch_bounds__(256) void kT_init()
{
    const int j  = threadIdx.x;
    const int c  = blockIdx.y;
    const int o0 = blockIdx.x * 4;
    const long src = (long)(c * CS + CS - 1) * MATSZ;
    const long dst = (long)c * MATSZ;
    #pragma unroll
    for (int r = 0; r < 4; ++r) {
        const long off = (long)(o0 + r) * DD + j;
        g_TP0[dst + off] = g_P [src + off];
        g_TS0[dst + off] = g_Ms[src + off];
    }
}

// ---------------------------------------------------------------------------
// Tree level: Kogge-Stone inclusive scan over (P,S) with
//   combine(first,second) = (P1@P2, S1@P2 + S2).
// For chunk c >= stride: dst_c = combine(src_{c-stride}, src_c); else copy.
// z = 0: P update; z = 1: S update. grid = (16 tiles, CH, 2), block = 256.
// ---------------------------------------------------------------------------
__global__ __launch_bounds__(256) void kT_combine(int stride, int srcIdx)
{
    const float* srcP = srcIdx ? g_TP1 : g_TP0;
    const float* srcS = srcIdx ? g_TS1 : g_TS0;
    float*       dstP = srcIdx ? g_TP0 : g_TP1;
    float*       dstS = srcIdx ? g_TS0 : g_TS1;

    const int c   = blockIdx.y;
    const int isS = blockIdx.z;
    const int ib  = blockIdx.x >> 2;
    const int jb  = blockIdx.x & 3;
    const int tid = threadIdx.x;

    const float* srcM = isS ? srcS : srcP;
    float*       dstM = isS ? dstS : dstP;

    if (c < stride) {   // pass-through copy of this 64x64 tile
        const int lr = tid >> 2;
        const int lc = tid & 3;
        const long base = (long)c * MATSZ;
        #pragma unroll
        for (int it = 0; it < 4; ++it) {
            const long off = base + (long)(ib * 64 + lr) * DD + jb * 64 + (lc + it * 4) * 4;
            *(float4*)(dstM + off) = *(const float4*)(srcM + off);
        }
        return;
    }

    __shared__ float sA[16][68];
    __shared__ float sB[16][68];

    const int lr = tid >> 2;
    const int lc = tid & 3;
    const int pr = tid >> 4;
    const int pc = tid & 15;
    const int tx = tid & 15;
    const int ty = tid >> 4;

    const float* A  = srcM + (long)(c - stride) * MATSZ;   // S_{c-s} or P_{c-s}
    const float* Bm = srcP + (long)c * MATSZ;              // P_c
    float*       Dm = dstM + (long)c * MATSZ;

    float acc[4][4];
    #pragma unroll
    for (int r = 0; r < 4; ++r)
        #pragma unroll
        for (int q = 0; q < 4; ++q) acc[r][q] = 0.f;

    const long arow = (long)(ib * 64 + lr) * DD;

    float4 av = *(const float4*)(A + arow + lc * 4);
    float4 bv = *(const float4*)(Bm + (long)pr * DD + jb * 64 + pc * 4);

    for (int ch = 0; ch < 16; ++ch) {
        sA[lc * 4 + 0][lr] = av.x; sA[lc * 4 + 1][lr] = av.y;
        sA[lc * 4 + 2][lr] = av.z; sA[lc * 4 + 3][lr] = av.w;
        sB[pr][pc * 4 + 0] = bv.x; sB[pr][pc * 4 + 1] = bv.y;
        sB[pr][pc * 4 + 2] = bv.z; sB[pr][pc * 4 + 3] = bv.w;
        __syncthreads();

        if (ch < 15) {
            av = *(const float4*)(A + arow + (ch + 1) * 16 + lc * 4);
            bv = *(const float4*)(Bm + (long)((ch + 1) * 16 + pr) * DD + jb * 64 + pc * 4);
        }

        #pragma unroll
        for (int dk = 0; dk < 16; ++dk) {
            float aw[4], bw[4];
            #pragma unroll
            for (int r = 0; r < 4; ++r) aw[r] = sA[dk][ty * 4 + r];
            #pragma unroll
            for (int q = 0; q < 4; ++q) bw[q] = sB[dk][tx * 4 + q];
            #pragma unroll
            for (int r = 0; r < 4; ++r)
                #pragma unroll
                for (int q = 0; q < 4; ++q) acc[r][q] += aw[r] * bw[q];
        }
        __syncthreads();
    }

    const float* C0 = isS ? (srcS + (long)c * MATSZ) : (const float*)0;
    #pragma unroll
    for (int r = 0; r < 4; ++r) {
        const long off = (long)(ib * 64 + ty * 4 + r) * DD + jb * 64 + tx * 4;
        float4 res = make_float4(acc[r][0], acc[r][1], acc[r][2], acc[r][3]);
        if (isS) {
            float4 c0 = *(const float4*)(C0 + off);
            res.x += c0.x; res.y += c0.y; res.z += c0.z; res.w += c0.w;
        }
        *(float4*)(Dm + off) = res;
    }
}

// ---------------------------------------------------------------------------
// Phase C: fix-up GEMMs (parallel): Ms[n] += E_{c-1} @ P_n for chunks 1..CH-1.
// E = final tree buffer (g_TS0). grid = (16 tiles, NW - CS), block = 256.
// ---------------------------------------------------------------------------
__global__ __launch_bounds__(256) void kC_fix()
{
    __shared__ float sE[16][68];
    __shared__ float sP[16][68];

    const int nw  = blockIdx.y + CS;
    const int c   = nw / CS;
    const int ib  = blockIdx.x >> 2;
    const int jb  = blockIdx.x & 3;
    const int tid = threadIdx.x;
    const int lr  = tid >> 2;
    const int lc  = tid & 3;
    const int pr  = tid >> 4;
    const int pc  = tid & 15;
    const int tx  = tid & 15;
    const int ty  = tid >> 4;

    const float* E = g_TS0 + (long)(c - 1) * MATSZ;
    const float* P = g_P + (long)nw * MATSZ;
    float*      Ms = g_Ms + (long)nw * MATSZ;

    float acc[4][4];
    #pragma unroll
    for (int r = 0; r < 4; ++r)
        #pragma unroll
        for (int q = 0; q < 4; ++q) acc[r][q] = 0.f;

    const long erow = (long)(ib * 64 + lr) * DD;

    float4 ev = *(const float4*)(E + erow + lc * 4);
    float4 pv = *(const float4*)(P + (long)pr * DD + jb * 64 + pc * 4);

    for (int ch = 0; ch < 16; ++ch) {
        sE[lc * 4 + 0][lr] = ev.x; sE[lc * 4 + 1][lr] = ev.y;
        sE[lc * 4 + 2][lr] = ev.z; sE[lc * 4 + 3][lr] = ev.w;
        sP[pr][pc * 4 + 0] = pv.x; sP[pr][pc * 4 + 1] = pv.y;
        sP[pr][pc * 4 + 2] = pv.z; sP[pr][pc * 4 + 3] = pv.w;
        __syncthreads();

        if (ch < 15) {
            ev = *(const float4*)(E + erow + (ch + 1) * 16 + lc * 4);
            pv = *(const float4*)(P + (long)((ch + 1) * 16 + pr) * DD + jb * 64 + pc * 4);
        }

        #pragma unroll
        for (int dk = 0; dk < 16; ++dk) {
            float aw[4], bw[4];
            #pragma unroll
            for (int r = 0; r < 4; ++r) aw[r] = sE[dk][ty * 4 + r];
            #pragma unroll
            for (int q = 0; q < 4; ++q) bw[q] = sP[dk][tx * 4 + q];
            #pragma unroll
            for (int r = 0; r < 4; ++r)
                #pragma unroll
                for (int q = 0; q < 4; ++q) acc[r][q] += aw[r] * bw[q];
        }
        __syncthreads();
    }

    #pragma unroll
    for (int r = 0; r < 4; ++r) {
        float* dst = Ms + (long)(ib * 64 + ty * 4 + r) * DD + jb * 64 + tx * 4;
        float4 old = *(const float4*)dst;
        *(float4*)dst = make_float4(old.x + acc[r][0], old.y + acc[r][1],
                                    old.z + acc[r][2], old.w + acc[r][3]);
    }
}

// ---------------------------------------------------------------------------
// K3: retrieval. out[t][o] = sum_d q[t][d] * Ms[n][o][d]
// ---------------------------------------------------------------------------
__global__ __launch_bounds__(256) void k3_out(
    const float* __restrict__ queries, float* __restrict__ out)
{
    __shared__ float sQ[16][68];
    __shared__ float sM[16][68];

    const int n   = blockIdx.y;
    const int tb  = blockIdx.x >> 2;
    const int ob  = blockIdx.x & 3;
    const int tid = threadIdx.x;
    const int lr  = tid >> 2;
    const int lc  = tid & 3;
    const int tx  = tid & 15;
    const int ty  = tid >> 4;

    const float* Ms = g_Ms + (long)n * MATSZ;

    float acc[4][4];
    #pragma unroll
    for (int r = 0; r < 4; ++r)
        #pragma unroll
        for (int c = 0; c < 4; ++c) acc[r][c] = 0.f;

    const int t_ld = tb * 64 + lr;
    const int b_ld = t_ld >> 6;
    const int w_ld = t_ld & 63;
    const long qrow = ((long)b_ld * LL + (long)n * WW + w_ld) * DD;
    const long mrow = (long)(ob * 64 + lr) * DD;

    float4 qv = *(const float4*)(queries + qrow + lc * 4);
    float4 mv = *(const float4*)(Ms + mrow + lc * 4);

    for (int ch = 0; ch < 16; ++ch) {
        sQ[lc * 4 + 0][lr] = qv.x; sQ[lc * 4 + 1][lr] = qv.y;
        sQ[lc * 4 + 2][lr] = qv.z; sQ[lc * 4 + 3][lr] = qv.w;
        sM[lc * 4 + 0][lr] = mv.x; sM[lc * 4 + 1][lr] = mv.y;
        sM[lc * 4 + 2][lr] = mv.z; sM[lc * 4 + 3][lr] = mv.w;
        __syncthreads();

        if (ch < 15) {
            qv = *(const float4*)(queries + qrow + (ch + 1) * 16 + lc * 4);
            mv = *(const float4*)(Ms + mrow + (ch + 1) * 16 + lc * 4);
        }

        #pragma unroll
        for (int dk = 0; dk < 16; ++dk) {
            float aw[4], bw[4];
            #pragma unroll
            for (int r = 0; r < 4; ++r) aw[r] = sQ[dk][ty * 4 + r];
            #pragma unroll
            for (int c = 0; c < 4; ++c) bw[c] = sM[dk][tx * 4 + c];
            #pragma unroll
            for (int r = 0; r < 4; ++r)
                #pragma unroll
                for (int c = 0; c < 4; ++c) acc[r][c] += aw[r] * bw[c];
        }
        __syncthreads();
    }

    #pragma unroll
    for (int r = 0; r < 4; ++r) {
        const int t = tb * 64 + ty * 4 + r;
        const int b = t >> 6;
        const int w = t & 63;
        const long addr = ((long)b * LL + (long)n * WW + w) * DD + ob * 64 + tx * 4;
        *(float4*)(out + addr) = make_float4(acc[r][0], acc[r][1], acc[r][2], acc[r][3]);
    }
}

// ---------------------------------------------------------------------------
extern "C" void kernel_launch(void* const* d_in, const int* in_sizes, int n_in,
                              void* d_out, int out_size)
{
    const float* keys    = (const float*)d_in[0];
    const float* values  = (const float*)d_in[1];
    const float* queries = (const float*)d_in[2];
    const float* gammas  = (const float*)d_in[3];
    const float* alpha   = (const float*)d_in[4];
    float* out = (float*)d_out;

    k1_moments<<<dim3(16, NW), 256>>>(keys, values, gammas);
    kA_local<<<dim3(64, CH), 256>>>(alpha);
    kT_init<<<dim3(64, CH), 256>>>();
    kT_combine<<<dim3(16, CH, 2), 256>>>(1, 0);  // buf0 -> buf1
    kT_combine<<<dim3(16, CH, 2), 256>>>(2, 1);  // buf1 -> buf0
    kT_combine<<<dim3(16, CH, 2), 256>>>(4, 0);  // buf0 -> buf1
    kT_combine<<<dim3(16, CH, 2), 256>>>(8, 1);  // buf1 -> buf0 (final: g_TS0)
    kC_fix<<<dim3(16, NW - CS), 256>>>();
    k3_out<<<dim3(32, NW), 256>>>(queries, out);
}